// round 1
// baseline (speedup 1.0000x reference)
#include <cuda_runtime.h>
#include <cuda_bf16.h>
#include <cstdint>

// Problem constants (fixed by the dataset reference):
//   feature        [32,512,512] f32      -> P = 8,388,608 points
//   indices        [32,512,512,3] i32    -> 3P ints
//   feature_volume [256,256,256] f32     -> V = 16,777,216 voxels
//   count_volume   [256,256,256] f32
//   output: concat(feature_volume', count_volume') -> 2V f32
#define DIM     256
#define V_TOTAL (DIM * DIM * DIM)

// Fused {sum, count} accumulator per voxel. Zero-initialized at module load;
// the finalize kernel restores zeros (only where touched) each launch, so
// every graph replay sees a clean scratch. No dummy slot needed: invalid
// points contribute exactly {0,0} in the reference, i.e. a no-op, so we skip
// their atomics instead of routing them to slot V.
__device__ __align__(16) float2 g_scratch[V_TOTAL];

// ---------------------------------------------------------------------------
// Pass A: scatter-add. 4 points per thread; indices read as 3x int4 (48B),
// features as float4. Both atomics for a point land in the same float2 ->
// same 32B sector -> one L2 RMW sector instead of two.
// ---------------------------------------------------------------------------
__global__ void __launch_bounds__(256) scatter_kernel(
    const float* __restrict__ feat,
    const int*   __restrict__ idx,
    int P4)
{
    int t = blockIdx.x * blockDim.x + threadIdx.x;
    if (t >= P4) return;

    const float4 f  = reinterpret_cast<const float4*>(feat)[t];
    const int4   i0 = reinterpret_cast<const int4*>(idx)[t * 3 + 0];
    const int4   i1 = reinterpret_cast<const int4*>(idx)[t * 3 + 1];
    const int4   i2 = reinterpret_cast<const int4*>(idx)[t * 3 + 2];

    const int xs[4] = { i0.x, i0.w, i1.z, i2.y };
    const int ys[4] = { i0.y, i1.x, i1.w, i2.z };
    const int zs[4] = { i0.z, i1.y, i2.x, i2.w };
    const float fv[4] = { f.x, f.y, f.z, f.w };

#pragma unroll
    for (int k = 0; k < 4; ++k) {
        const int x = xs[k], y = ys[k], z = zs[k];
        const bool valid = ((unsigned)x < (unsigned)DIM) &
                           ((unsigned)y < (unsigned)DIM) &
                           ((unsigned)z < (unsigned)DIM);
        if (valid) {
            const int flat = (((x << 8) | y) << 8) | z;
            atomicAdd(&g_scratch[flat].x, fv[k]);
            atomicAdd(&g_scratch[flat].y, 1.0f);
        }
    }
}

// ---------------------------------------------------------------------------
// Pass B: per-voxel finalize. 4 voxels per thread, all float4 traffic.
//   touched  : fv' = fv*cv + (sum/cnt)/(cv+1) ; cv' = cv+1 ; scratch := 0
//   untouched: copy-through, no scratch write (it is already zero).
// ---------------------------------------------------------------------------
__global__ void __launch_bounds__(256) finalize_kernel(
    const float* __restrict__ fvol,
    const float* __restrict__ cvol,
    float*       __restrict__ out,
    int V4)
{
    int t = blockIdx.x * blockDim.x + threadIdx.x;
    if (t >= V4) return;

    const float4 a = reinterpret_cast<const float4*>(fvol)[t];
    const float4 c = reinterpret_cast<const float4*>(cvol)[t];

    float4* scr4 = reinterpret_cast<float4*>(g_scratch);
    const float4 s01 = scr4[2 * t + 0];   // {sum0,cnt0,sum1,cnt1}
    const float4 s23 = scr4[2 * t + 1];   // {sum2,cnt2,sum3,cnt3}

    const float sum[4] = { s01.x, s01.z, s23.x, s23.z };
    const float cnt[4] = { s01.y, s01.w, s23.y, s23.w };
    const float fa[4]  = { a.x, a.y, a.z, a.w };
    const float cc[4]  = { c.x, c.y, c.z, c.w };

    float of[4], oc[4];
    bool touched = false;
#pragma unroll
    for (int k = 0; k < 4; ++k) {
        if (cnt[k] > 0.0f) {
            touched = true;
            const float cn = cc[k] + 1.0f;
            of[k] = fa[k] * cc[k] + (sum[k] / cnt[k]) / cn;
            oc[k] = cn;
        } else {
            of[k] = fa[k];
            oc[k] = cc[k];
        }
    }

    reinterpret_cast<float4*>(out)[t]           = make_float4(of[0], of[1], of[2], of[3]);
    reinterpret_cast<float4*>(out + V_TOTAL)[t] = make_float4(oc[0], oc[1], oc[2], oc[3]);

    if (touched) {
        const float4 z = make_float4(0.f, 0.f, 0.f, 0.f);
        scr4[2 * t + 0] = z;
        scr4[2 * t + 1] = z;
    }
}

extern "C" void kernel_launch(void* const* d_in, const int* in_sizes, int n_in,
                              void* d_out, int out_size)
{
    const float* feat = (const float*)d_in[0];   // [P]
    const int*   idx  = (const int*)d_in[1];     // [P,3]
    const float* fvol = (const float*)d_in[2];   // [V]
    const float* cvol = (const float*)d_in[3];   // [V]
    float*       out  = (float*)d_out;           // [2V]

    const int P  = in_sizes[0];                  // 8,388,608 (divisible by 4)
    const int P4 = P / 4;
    const int V4 = V_TOTAL / 4;

    scatter_kernel<<<(P4 + 255) / 256, 256>>>(feat, idx, P4);
    finalize_kernel<<<(V4 + 255) / 256, 256>>>(fvol, cvol, out, V4);
}

// round 4
// speedup vs baseline: 1.2179x; 1.2179x over previous
#include <cuda_runtime.h>
#include <cuda_bf16.h>
#include <cstdint>

// Problem constants (fixed by the dataset reference):
//   feature        [32,512,512] f32      -> P = 8,388,608 points
//   indices        [32,512,512,3] i32    -> 3P ints
//   feature_volume [256,256,256] f32     -> V = 16,777,216 voxels
//   count_volume   [256,256,256] f32
//   output: concat(feature_volume', count_volume') -> 2V f32
#define DIM     256
#define V_TOTAL (DIM * DIM * DIM)

// Fused {sum, count} accumulator per voxel. Zero-initialized at module load;
// the finalize kernel restores zeros (only where touched), so every graph
// replay sees a clean scratch. Invalid points contribute exactly {0,0} in
// the reference (a no-op), so we skip their atomics.
__device__ __align__(16) float2 g_scratch[V_TOTAL];

// Single 64-bit reduction: red.global.add.v2.f32 (PTX ISA 8.1, sm_90+).
// One RED to one 8B-aligned address instead of two scalar RED.F32.
__device__ __forceinline__ void red_add_f32x2(float2* addr, float a, float b)
{
    asm volatile("red.global.add.v2.f32 [%0], {%1, %2};"
                 :: "l"(addr), "f"(a), "f"(b) : "memory");
}

// ---------------------------------------------------------------------------
// Pass A: scatter-add. 4 points/thread. Inputs loaded with __ldcs
// (evict-first) so the 134 MB input stream does not evict scratch sectors
// from L2 between atomic RMWs. One vector RED per point.
// ---------------------------------------------------------------------------
__global__ void __launch_bounds__(256) scatter_kernel(
    const float* __restrict__ feat,
    const int*   __restrict__ idx,
    int P4)
{
    int t = blockIdx.x * blockDim.x + threadIdx.x;
    if (t >= P4) return;

    const float4 f  = __ldcs(reinterpret_cast<const float4*>(feat) + t);
    const int4   i0 = __ldcs(reinterpret_cast<const int4*>(idx) + t * 3 + 0);
    const int4   i1 = __ldcs(reinterpret_cast<const int4*>(idx) + t * 3 + 1);
    const int4   i2 = __ldcs(reinterpret_cast<const int4*>(idx) + t * 3 + 2);

    const int xs[4] = { i0.x, i0.w, i1.z, i2.y };
    const int ys[4] = { i0.y, i1.x, i1.w, i2.z };
    const int zs[4] = { i0.z, i1.y, i2.x, i2.w };
    const float fv[4] = { f.x, f.y, f.z, f.w };

#pragma unroll
    for (int k = 0; k < 4; ++k) {
        const int x = xs[k], y = ys[k], z = zs[k];
        const bool valid = ((unsigned)x < (unsigned)DIM) &
                           ((unsigned)y < (unsigned)DIM) &
                           ((unsigned)z < (unsigned)DIM);
        if (valid) {
            const int flat = (((x << 8) | y) << 8) | z;
            red_add_f32x2(&g_scratch[flat], fv[k], 1.0f);
        }
    }
}

// ---------------------------------------------------------------------------
// Pass B: per-voxel finalize. 4 voxels/thread, all float4 traffic.
//   touched  : fv' = fv*cv + (sum/cnt)/(cv+1) ; cv' = cv+1
//   untouched: copy-through.
// Scratch re-zero at 16B granule (2 voxels): write zeros only if that half
// was touched (prob 1-0.61^2 = 0.63 vs 0.86 at 32B granule).
// Output written with __stcs (streaming) — read-never data, keep L2 clean.
// ---------------------------------------------------------------------------
__global__ void __launch_bounds__(256) finalize_kernel(
    const float* __restrict__ fvol,
    const float* __restrict__ cvol,
    float*       __restrict__ out,
    int V4)
{
    int t = blockIdx.x * blockDim.x + threadIdx.x;
    if (t >= V4) return;

    const float4 a = __ldcs(reinterpret_cast<const float4*>(fvol) + t);
    const float4 c = __ldcs(reinterpret_cast<const float4*>(cvol) + t);

    float4* scr4 = reinterpret_cast<float4*>(g_scratch);
    const float4 s01 = scr4[2 * t + 0];   // {sum0,cnt0,sum1,cnt1}
    const float4 s23 = scr4[2 * t + 1];   // {sum2,cnt2,sum3,cnt3}

    const float sum[4] = { s01.x, s01.z, s23.x, s23.z };
    const float cnt[4] = { s01.y, s01.w, s23.y, s23.w };
    const float fa[4]  = { a.x, a.y, a.z, a.w };
    const float cc[4]  = { c.x, c.y, c.z, c.w };

    float of[4], oc[4];
#pragma unroll
    for (int k = 0; k < 4; ++k) {
        if (cnt[k] > 0.0f) {
            const float cn = cc[k] + 1.0f;
            of[k] = fa[k] * cc[k] + (sum[k] / cnt[k]) / cn;
            oc[k] = cn;
        } else {
            of[k] = fa[k];
            oc[k] = cc[k];
        }
    }

    __stcs(reinterpret_cast<float4*>(out) + t,
           make_float4(of[0], of[1], of[2], of[3]));
    __stcs(reinterpret_cast<float4*>(out + V_TOTAL) + t,
           make_float4(oc[0], oc[1], oc[2], oc[3]));

    const float4 z = make_float4(0.f, 0.f, 0.f, 0.f);
    if (cnt[0] > 0.0f || cnt[1] > 0.0f) scr4[2 * t + 0] = z;
    if (cnt[2] > 0.0f || cnt[3] > 0.0f) scr4[2 * t + 1] = z;
}

extern "C" void kernel_launch(void* const* d_in, const int* in_sizes, int n_in,
                              void* d_out, int out_size)
{
    const float* feat = (const float*)d_in[0];   // [P]
    const int*   idx  = (const int*)d_in[1];     // [P,3]
    const float* fvol = (const float*)d_in[2];   // [V]
    const float* cvol = (const float*)d_in[3];   // [V]
    float*       out  = (float*)d_out;           // [2V]

    const int P  = in_sizes[0];                  // 8,388,608 (divisible by 4)
    const int P4 = (P + 3) / 4;                  // exact for this dataset
    const int V4 = V_TOTAL / 4;

    scatter_kernel<<<(P4 + 255) / 256, 256>>>(feat, idx, P4);
    finalize_kernel<<<(V4 + 255) / 256, 256>>>(fvol, cvol, out, V4);
}

// round 5
// speedup vs baseline: 1.7785x; 1.4603x over previous
#include <cuda_runtime.h>
#include <cuda_bf16.h>
#include <cstdint>

// Problem constants (fixed by the dataset reference):
//   feature        [32,512,512] f32      -> P = 8,388,608 points
//   indices        [32,512,512,3] i32    -> 3P ints
//   feature_volume [256,256,256] f32     -> V = 16,777,216 voxels
//   count_volume   [256,256,256] f32
//   output: concat(feature_volume', count_volume') -> 2V f32
#define DIM     256
#define V_TOTAL (DIM * DIM * DIM)
#define V_HALF  (V_TOTAL / 2)

// Fused {sum, count} accumulator per voxel. Explicitly zeroed by zero_kernel
// before each scatter pass (graph-replayed prologue), so no residual-state
// tricks are needed and finalize does no restore.
__device__ __align__(16) float2 g_scratch[V_TOTAL];

// Single 64-bit reduction: red.global.add.v2.f32 (sm_90+).
__device__ __forceinline__ void red_add_f32x2(float2* addr, float a, float b)
{
    asm volatile("red.global.add.v2.f32 [%0], {%1, %2};"
                 :: "l"(addr), "f"(a), "f"(b) : "memory");
}

// ---------------------------------------------------------------------------
// Zero one half of scratch with full-line stores. Full 32B-sector writes
// write-allocate in L2 WITHOUT DRAM fills and leave the lines resident+dirty,
// so the scatter pass's REDs never fill from DRAM.
// ---------------------------------------------------------------------------
__global__ void __launch_bounds__(256) zero_kernel(int half)
{
    const int t = blockIdx.x * blockDim.x + threadIdx.x;
    // half of scratch = V_HALF voxels * 8B = 67 MB = V_HALF/2 float4s
    float4* dst = reinterpret_cast<float4*>(g_scratch + (size_t)half * V_HALF);
    dst[t] = make_float4(0.f, 0.f, 0.f, 0.f);
}

// ---------------------------------------------------------------------------
// Scatter pass for one volume half (x>>7 == half): the RMW working set is
// 67 MB and stays L2-resident. Inputs streamed with __ldcs (evict-first) so
// they do not evict scratch. One vector RED per in-half point.
// ---------------------------------------------------------------------------
__global__ void __launch_bounds__(256) scatter_kernel(
    const float* __restrict__ feat,
    const int*   __restrict__ idx,
    int P4, int half)
{
    int t = blockIdx.x * blockDim.x + threadIdx.x;
    if (t >= P4) return;

    const float4 f  = __ldcs(reinterpret_cast<const float4*>(feat) + t);
    const int4   i0 = __ldcs(reinterpret_cast<const int4*>(idx) + t * 3 + 0);
    const int4   i1 = __ldcs(reinterpret_cast<const int4*>(idx) + t * 3 + 1);
    const int4   i2 = __ldcs(reinterpret_cast<const int4*>(idx) + t * 3 + 2);

    const int xs[4] = { i0.x, i0.w, i1.z, i2.y };
    const int ys[4] = { i0.y, i1.x, i1.w, i2.z };
    const int zs[4] = { i0.z, i1.y, i2.x, i2.w };
    const float fv[4] = { f.x, f.y, f.z, f.w };

#pragma unroll
    for (int k = 0; k < 4; ++k) {
        const int x = xs[k], y = ys[k], z = zs[k];
        const bool valid = ((unsigned)x < (unsigned)DIM) &
                           ((unsigned)y < (unsigned)DIM) &
                           ((unsigned)z < (unsigned)DIM) &
                           ((x >> 7) == half);
        if (valid) {
            const int flat = (((x << 8) | y) << 8) | z;
            red_add_f32x2(&g_scratch[flat], fv[k], 1.0f);
        }
    }
}

// ---------------------------------------------------------------------------
// Finalize: per-voxel, 4 voxels/thread, all float4 traffic. No scratch
// restore (zeroing is an explicit prologue now).
//   touched  : fv' = fv*cv + (sum/cnt)/(cv+1) ; cv' = cv+1
//   untouched: copy-through.
// ---------------------------------------------------------------------------
__global__ void __launch_bounds__(256) finalize_kernel(
    const float* __restrict__ fvol,
    const float* __restrict__ cvol,
    float*       __restrict__ out,
    int V4)
{
    int t = blockIdx.x * blockDim.x + threadIdx.x;
    if (t >= V4) return;

    const float4 a = __ldcs(reinterpret_cast<const float4*>(fvol) + t);
    const float4 c = __ldcs(reinterpret_cast<const float4*>(cvol) + t);

    const float4* scr4 = reinterpret_cast<const float4*>(g_scratch);
    const float4 s01 = __ldcs(scr4 + 2 * t + 0);  // {sum0,cnt0,sum1,cnt1}
    const float4 s23 = __ldcs(scr4 + 2 * t + 1);  // {sum2,cnt2,sum3,cnt3}

    const float sum[4] = { s01.x, s01.z, s23.x, s23.z };
    const float cnt[4] = { s01.y, s01.w, s23.y, s23.w };
    const float fa[4]  = { a.x, a.y, a.z, a.w };
    const float cc[4]  = { c.x, c.y, c.z, c.w };

    float of[4], oc[4];
#pragma unroll
    for (int k = 0; k < 4; ++k) {
        if (cnt[k] > 0.0f) {
            const float cn = cc[k] + 1.0f;
            of[k] = fa[k] * cc[k] + (sum[k] / cnt[k]) / cn;
            oc[k] = cn;
        } else {
            of[k] = fa[k];
            oc[k] = cc[k];
        }
    }

    __stcs(reinterpret_cast<float4*>(out) + t,
           make_float4(of[0], of[1], of[2], of[3]));
    __stcs(reinterpret_cast<float4*>(out + V_TOTAL) + t,
           make_float4(oc[0], oc[1], oc[2], oc[3]));
}

extern "C" void kernel_launch(void* const* d_in, const int* in_sizes, int n_in,
                              void* d_out, int out_size)
{
    const float* feat = (const float*)d_in[0];   // [P]
    const int*   idx  = (const int*)d_in[1];     // [P,3]
    const float* fvol = (const float*)d_in[2];   // [V]
    const float* cvol = (const float*)d_in[3];   // [V]
    float*       out  = (float*)d_out;           // [2V]

    const int P  = in_sizes[0];                  // 8,388,608 (divisible by 4)
    const int P4 = (P + 3) / 4;
    const int V4 = V_TOTAL / 4;
    const int Z4 = V_HALF / 2;                   // float4 count per half

    // Pass over each volume half: zero its scratch (L2-resident, no fills),
    // then scatter only that half's points.
    zero_kernel<<<Z4 / 256, 256>>>(0);
    scatter_kernel<<<(P4 + 255) / 256, 256>>>(feat, idx, P4, 0);
    zero_kernel<<<Z4 / 256, 256>>>(1);
    scatter_kernel<<<(P4 + 255) / 256, 256>>>(feat, idx, P4, 1);

    finalize_kernel<<<(V4 + 255) / 256, 256>>>(fvol, cvol, out, V4);
}